// round 14
// baseline (speedup 1.0000x reference)
#include <cuda_runtime.h>
#include <cuda_bf16.h>
#include <cstdint>
#include <math.h>

#define KD 512
#define DZ 256
#define NR 32768

// smem map (bytes): RA [0,69632)  RB [69632,200704)  MISC [200704,203552)
#define RBOFF 69632
#define MISCOFF 200704
#define SMTOT 203552

__device__ __forceinline__ uint32_t s2u(const void* p){
    uint32_t a;
    asm("{ .reg .u64 t; cvta.to.shared.u64 t,%1; cvt.u32.u64 %0,t; }" : "=r"(a) : "l"(p));
    return a;
}
__device__ __forceinline__ void ldsm4(uint32_t r[4], uint32_t a){
    asm volatile("ldmatrix.sync.aligned.m8n8.x4.shared.b16 {%0,%1,%2,%3}, [%4];"
        : "=r"(r[0]),"=r"(r[1]),"=r"(r[2]),"=r"(r[3]) : "r"(a));
}
__device__ __forceinline__ void mma_bf(float d[4], const uint32_t a[4], uint32_t b0, uint32_t b1){
    asm volatile("mma.sync.aligned.m16n8k16.row.col.f32.bf16.bf16.f32 "
        "{%0,%1,%2,%3},{%4,%5,%6,%7},{%8,%9},{%0,%1,%2,%3};"
        : "+f"(d[0]),"+f"(d[1]),"+f"(d[2]),"+f"(d[3])
        : "r"(a[0]),"r"(a[1]),"r"(a[2]),"r"(a[3]),"r"(b0),"r"(b1));
}
__device__ __forceinline__ void cpa16(uint32_t dst, const void* src){
    asm volatile("cp.async.cg.shared.global [%0], [%1], 16;" :: "r"(dst), "l"(src));
}
#define CPA_COMMIT() asm volatile("cp.async.commit_group;" ::: "memory")
#define CPA_WAIT0()  asm volatile("cp.async.wait_group 0;" ::: "memory")
#define CPA_WAIT1()  asm volatile("cp.async.wait_group 1;" ::: "memory")
#define PFL2(p)      asm volatile("prefetch.global.L2 [%0];" :: "l"(p))

__device__ __forceinline__ uint32_t packpair(float lo, float hi){
    uint32_t r; asm("cvt.rn.bf16x2.f32 %0, %1, %2;" : "=r"(r) : "f"(hi), "f"(lo)); return r;
}
__device__ __forceinline__ float lof(float x){
    return x - __bfloat162float(__float2bfloat16(x));
}

__device__ uint32_t g_c1h[KD*128];    // kq*cbn [n=512][kpair=128]
__device__ uint32_t g_c1l[KD*128];
__device__ uint32_t g_c2h[DZ*256];    // cbn^T  [d=256][jpair=256]
__device__ uint32_t g_c2l[DZ*256];
__device__ float    g_cbn[KD*DZ];
__device__ float    g_avg[KD];
__device__ float    g_kldd, g_kldc;

__global__ void k_zero(){
    int t=threadIdx.x;
    if (t<KD) g_avg[t]=0.f;
    if (t==0){ g_kldd=0.f; g_kldc=0.f; }
}

__global__ void k_norm(const float* __restrict__ cb, const float* __restrict__ kappa){
    __shared__ float rowb[256];
    __shared__ float ws[8];
    int j=blockIdx.x, t=threadIdx.x;
    float c=cb[j*DZ+t], s=c*c;
    #pragma unroll
    for(int o=16;o;o>>=1) s += __shfl_xor_sync(0xffffffffu,s,o);
    if((t&31)==0) ws[t>>5]=s;
    __syncthreads();
    float tot=0.f;
    #pragma unroll
    for(int i=0;i<8;i++) tot+=ws[i];
    float cn=c*(1.f/sqrtf(tot));
    g_cbn[j*DZ+t]=cn;
    float kq=fminf(fmaxf(kappa[0],1e-5f),1e5f);
    rowb[t]=cn*kq;
    __syncthreads();
    if(t<128){
        float a=rowb[2*t], b=rowb[2*t+1];
        g_c1h[j*128+t]=packpair(a,b);
        g_c1l[j*128+t]=packpair(lof(a),lof(b));
    }
}

__global__ void k_c2(){
    int d=blockIdx.x, t=threadIdx.x;   // t = jpair
    float a=g_cbn[(2*t)*DZ+d], b=g_cbn[(2*t+1)*DZ+d];
    g_c2h[d*256+t]=packpair(a,b);
    g_c2l[d*256+t]=packpair(lof(a),lof(b));
}

// ---- k32-chunk staging: 64B rows, swizzle gr^((n>>1)&3), h+l one group ----
__device__ __forceinline__ void stage1(uint32_t smb, int t, int kc, uint32_t buf){
    #pragma unroll
    for(int i=0;i<4;i++){
        int q=t+(i<<9); int n=q>>2, gr=q&3;
        uint32_t off = buf + n*64 + ((uint32_t)(gr^((n>>1)&3))<<4);
        size_t so = (size_t)n*512 + kc*64 + gr*16;
        cpa16(smb+off,        (const char*)g_c1h + so);
        cpa16(smb+off+32768,  (const char*)g_c1l + so);
    }
}
__device__ __forceinline__ void stage2(uint32_t smb, int t, int kc, uint32_t buf){
    #pragma unroll
    for(int i=0;i<2;i++){
        int q=t+(i<<9); int dd=q>>2, gr=q&3;
        uint32_t off = buf + dd*64 + ((uint32_t)(gr^((dd>>1)&3))<<4);
        size_t so = (size_t)dd*1024 + kc*64 + gr*16;
        cpa16(smb+off,        (const char*)g_c2h + so);
        cpa16(smb+off+16384,  (const char*)g_c2l + so);
    }
}

__global__ __launch_bounds__(512,1)
void k_main(const float* __restrict__ gu, const float* __restrict__ z,
            float* __restrict__ out){
    extern __shared__ char sm[];
    const uint32_t smb=s2u(sm);
    float* MISC=(float*)(sm+MISCOFF);
    float* sZs=MISC; float* sSs=MISC+64; float* sZ2=MISC+128;
    float* sRed=MISC+192;
    const int t=threadIdx.x, lane=t&31, w=t>>5;     // 16 warps
    const int mg=w&1, ns=w>>1;                      // mg 0/1, ns 0..7
    const int g=lane>>2, tq=lane&3;
    const int R0=blockIdx.x<<6;
    if(t<64){ sZs[t]=0.f; sSs[t]=0.f; sZ2[t]=0.f; }

    const size_t bb=(size_t)(R0>>10);
    const int wh0=R0&1023;
    const float* zb = z + bb*262144 + wh0;

    // ---- prologue: z slab -> RB buf1 (64KB); B1 chunk0 -> RB buf0 ----
    #pragma unroll
    for(int i=0;i<8;i++){
        int q=t+(i<<9); int d=q>>4, j4=q&15;
        cpa16(smb + RBOFF + 65536 + (q<<4),
              (const char*)zb + ((size_t)d*4096 + j4*16));
    }
    CPA_COMMIT();
    stage1(smb,t,0,RBOFF); CPA_COMMIT();
    CPA_WAIT1(); __syncthreads();                    // z ready

    // ---- pack A tiles (hi at RA[0,32K), lo at RA[32K,64K)) ----
    {
        const float* sZf=(const float*)(sm + RBOFF + 65536);
        #pragma unroll
        for(int i=0;i<4;i++){
            int m=(t&31)+((i&1)<<5);
            int gr=(t>>5)+((i>>1)<<4);
            float v[8];
            #pragma unroll
            for(int c=0;c<8;c++) v[c]=sZf[(8*gr+c)*64 + m];
            int swz=(gr&24)|((gr^m)&7);
            uint32_t off=(uint32_t)(m*512 + (swz<<4));
            *(uint4*)(sm + off)=make_uint4(packpair(v[0],v[1]),packpair(v[2],v[3]),
                                           packpair(v[4],v[5]),packpair(v[6],v[7]));
            *(uint4*)(sm + 32768 + off)=make_uint4(packpair(lof(v[0]),lof(v[1])),packpair(lof(v[2]),lof(v[3])),
                                                   packpair(lof(v[4]),lof(v[5])),packpair(lof(v[6]),lof(v[7])));
        }
    }
    // gu L2 prefetch (4 rows x 256B per thread)
    {
        const float* p0=gu+(size_t)(R0+mg*32+g)*512+ns*64;
        PFL2(p0); PFL2(p0+32);
        PFL2(p0+8*512); PFL2(p0+8*512+32);
        const float* p2=p0+16*512;
        PFL2(p2); PFL2(p2+32);
        PFL2(p2+8*512); PFL2(p2+8*512+32);
    }
    __syncthreads();                                 // pack done; buf1 free

    const int sub=lane>>3, rro=(lane&7)+((sub&1)<<3), gpl=sub>>1;

    float a1[2][8][4];
    #pragma unroll
    for(int a=0;a<2;a++)
        #pragma unroll
        for(int b=0;b<8;b++)
            #pragma unroll
            for(int c=0;c<4;c++) a1[a][b][c]=0.f;

    // -------- GEMM1: 8 k32 chunks, double-buffered, merged h+l passes --------
    #pragma unroll
    for(int kc=0;kc<8;kc++){
        const uint32_t buf = RBOFF + (uint32_t)(kc&1)*65536;
        CPA_WAIT0(); __syncthreads();                // chunk kc ready; prev compute done
        if(kc<7){ stage1(smb,t,kc+1,RBOFF + (uint32_t)((kc&1)^1)*65536); CPA_COMMIT(); }
        #pragma unroll
        for(int ks=0;ks<2;ks++){
            int ggA=kc*4+2*ks+gpl, ggB=2*ks+gpl;
            uint32_t ah[2][4], al[2][4];
            #pragma unroll
            for(int mt=0;mt<2;mt++){
                int rr=mg*32+mt*16+rro;
                uint32_t ad=smb + rr*512 + ((((ggA&24)|((ggA^rr)&7)))<<4);
                ldsm4(ah[mt],ad); ldsm4(al[mt],ad+32768);
            }
            #pragma unroll
            for(int nt2=0;nt2<4;nt2++){
                int rrB=ns*64+nt2*16+rro;
                uint32_t bd=smb + buf + rrB*64 + ((uint32_t)(ggB^((rrB>>1)&3))<<4);
                uint32_t bh[4], bl[4];
                ldsm4(bh,bd); ldsm4(bl,bd+32768);
                #pragma unroll
                for(int mt=0;mt<2;mt++){
                    mma_bf(a1[mt][2*nt2],   ah[mt], bh[0], bh[2]);
                    mma_bf(a1[mt][2*nt2+1], ah[mt], bh[1], bh[3]);
                    mma_bf(a1[mt][2*nt2],   al[mt], bh[0], bh[2]);
                    mma_bf(a1[mt][2*nt2+1], al[mt], bh[1], bh[3]);
                    mma_bf(a1[mt][2*nt2],   ah[mt], bl[0], bl[2]);
                    mma_bf(a1[mt][2*nt2+1], ah[mt], bl[1], bl[3]);
                }
            }
        }
    }
    __syncthreads();                                 // GEMM1 reads done (RA+RB free)

    // ---- GEMM2 chunk0 staging flows during softmax ----
    stage2(smb,t,0,0); CPA_COMMIT();

    // -------- softmax + gumbel (from regs); eg->RB bf16 hi/lo --------
    #pragma unroll
    for(int mt=0;mt<2;mt++){
        int r0=mg*32+mt*16+g, r1=r0+8;
        const float* gur0 = gu + (size_t)(R0+r0)*512 + ns*64 + 2*tq;
        const float* gur1 = gu + (size_t)(R0+r1)*512 + ns*64 + 2*tq;
        float2 nu0=*(const float2*)gur0, nu1=*(const float2*)gur1;
        float Zs0=0,Ss0=0,Q0=0, Zs1=0,Ss1=0,Q1=0;
        #pragma unroll
        for(int nt=0;nt<8;nt++){
            float2 u0=nu0, u1=nu1;
            if(nt<7){ nu0=*(const float2*)(gur0+(nt+1)*8); nu1=*(const float2*)(gur1+(nt+1)*8); }
            int col=ns*64+nt*8+2*tq;
            float* dd=a1[mt][nt];
            float e0=__expf(dd[0]), e1=__expf(dd[1]);
            float e2=__expf(dd[2]), e3=__expf(dd[3]);
            Zs0+=e0+e1; Ss0+=e0*dd[0]+e1*dd[1];
            Zs1+=e2+e3; Ss1+=e2*dd[2]+e3*dd[3];
            float w0=-__logf(u0.x+1e-10f), w1=-__logf(u0.y+1e-10f);
            float w2=-__logf(u1.x+1e-10f), w3=-__logf(u1.y+1e-10f);
            float v0=__fdividef(e0,w0+1e-10f), v1=__fdividef(e1,w1+1e-10f);
            float v2=__fdividef(e2,w2+1e-10f), v3=__fdividef(e3,w3+1e-10f);
            float q0=v0*v0,q1=v1*v1,q2=v2*v2,q3=v3*v3;
            Q0+=q0+q1; Q1+=q2+q3;
            int gf=col>>3; int swz=(gf&56)|((gf^(r0&7))&7);
            uint32_t off=(uint32_t)(swz<<4)+4*tq;
            *(uint32_t*)(sm + RBOFF + r0*1024 + off)=packpair(q0,q1);
            *(uint32_t*)(sm + RBOFF + 65536 + r0*1024 + off)=packpair(lof(q0),lof(q1));
            *(uint32_t*)(sm + RBOFF + r1*1024 + off)=packpair(q2,q3);
            *(uint32_t*)(sm + RBOFF + 65536 + r1*1024 + off)=packpair(lof(q2),lof(q3));
        }
        atomicAdd(&sZs[r0],Zs0); atomicAdd(&sSs[r0],Ss0); atomicAdd(&sZ2[r0],Q0);
        atomicAdd(&sZs[r1],Zs1); atomicAdd(&sSs[r1],Ss1); atomicAdd(&sZ2[r1],Q1);
    }
    __syncthreads();
    if(t<64){
        float zs=sZs[t], inv=1.f/zs;
        float kd=sSs[t]*inv-__logf(zs);
        sZs[t]=inv;
        sZ2[t]=1.f/sZ2[t];
        #pragma unroll
        for(int o=16;o;o>>=1) kd+=__shfl_xor_sync(0xffffffffu,kd,o);
        if(lane==0) atomicAdd(&g_kldd,kd);
    }
    __syncthreads();
    {   // avg_probs: recompute e from live a1 regs, column-reduce via shfl
        float pcol[16];
        #pragma unroll
        for(int i=0;i<16;i++) pcol[i]=0.f;
        #pragma unroll
        for(int mt=0;mt<2;mt++){
            int r0=mg*32+mt*16+g;
            float zi0=sZs[r0], zi1=sZs[r0+8];
            #pragma unroll
            for(int nt=0;nt<8;nt++){
                float* dd=a1[mt][nt];
                pcol[2*nt]   += __expf(dd[0])*zi0 + __expf(dd[2])*zi1;
                pcol[2*nt+1] += __expf(dd[1])*zi0 + __expf(dd[3])*zi1;
            }
        }
        #pragma unroll
        for(int o=4;o<32;o<<=1)
            #pragma unroll
            for(int i=0;i<16;i++) pcol[i]+=__shfl_xor_sync(0xffffffffu,pcol[i],o);
        if(lane<4){
            #pragma unroll
            for(int nt=0;nt<8;nt++){
                int col=ns*64+nt*8+2*lane;
                atomicAdd(&g_avg[col],  pcol[2*nt]);
                atomicAdd(&g_avg[col+1],pcol[2*nt+1]);
            }
        }
    }

    // -------- GEMM2: 16 k32 chunks, double-buffered in RA, merged passes --------
    float a2[2][4][4];
    #pragma unroll
    for(int a=0;a<2;a++)
        #pragma unroll
        for(int b=0;b<4;b++)
            #pragma unroll
            for(int c=0;c<4;c++) a2[a][b][c]=0.f;

    #pragma unroll
    for(int kc=0;kc<16;kc++){
        const uint32_t buf = (uint32_t)(kc&1)*32768;
        CPA_WAIT0(); __syncthreads();                // chunk kc ready; eg visible (first iter)
        if(kc<15){ stage2(smb,t,kc+1,(uint32_t)((kc&1)^1)*32768); CPA_COMMIT(); }
        #pragma unroll
        for(int ks=0;ks<2;ks++){
            int ggE=kc*4+2*ks+gpl, ggB=2*ks+gpl;
            uint32_t eh[2][4], el[2][4];
            #pragma unroll
            for(int mt=0;mt<2;mt++){
                int rr=mg*32+mt*16+rro;
                uint32_t ad=smb + RBOFF + rr*1024 + ((((ggE&56)|((ggE^rr)&7)))<<4);
                ldsm4(eh[mt],ad); ldsm4(el[mt],ad+65536);
            }
            #pragma unroll
            for(int nt2=0;nt2<2;nt2++){
                int rrB=ns*32+nt2*16+rro;
                uint32_t bd=smb + buf + rrB*64 + ((uint32_t)(ggB^((rrB>>1)&3))<<4);
                uint32_t bh[4], bl[4];
                ldsm4(bh,bd); ldsm4(bl,bd+16384);
                #pragma unroll
                for(int mt=0;mt<2;mt++){
                    mma_bf(a2[mt][2*nt2],   eh[mt], bh[0], bh[2]);
                    mma_bf(a2[mt][2*nt2+1], eh[mt], bh[1], bh[3]);
                    mma_bf(a2[mt][2*nt2],   el[mt], bh[0], bh[2]);
                    mma_bf(a2[mt][2*nt2+1], el[mt], bh[1], bh[3]);
                    mma_bf(a2[mt][2*nt2],   eh[mt], bl[0], bl[2]);
                    mma_bf(a2[mt][2*nt2+1], eh[mt], bl[1], bl[3]);
                }
            }
        }
    }
    __syncthreads();

    // -------- epilogue: scale, transpose, coalesced store + kldc --------
    float* sT=(float*)sm;   // [256 d][66]
    #pragma unroll
    for(int mt=0;mt<2;mt++){
        int r0=mg*32+mt*16+g, r1=r0+8;
        float zi0=sZ2[r0], zi1=sZ2[r1];
        #pragma unroll
        for(int nt=0;nt<4;nt++){
            int d0=ns*32+nt*8+2*tq;
            float* dd=a2[mt][nt];
            sT[d0*66+r0]=dd[0]*zi0; sT[(d0+1)*66+r0]=dd[1]*zi0;
            sT[d0*66+r1]=dd[2]*zi1; sT[(d0+1)*66+r1]=dd[3]*zi1;
        }
    }
    __syncthreads();
    size_t base=bb*262144 + (size_t)wh0;
    float kcc=0.f;
    #pragma unroll
    for(int i=0;i<32;i++){
        int q=t+(i<<9); int d=q>>6, r=q&63;
        float v=sT[d*66+r];
        size_t gi=base+(size_t)d*1024+r;
        float zv=z[gi];
        out[gi]=v;
        kcc=fmaf(zv,zv-v,kcc);
    }
    #pragma unroll
    for(int o=16;o;o>>=1) kcc+=__shfl_xor_sync(0xffffffffu,kcc,o);
    if(lane==0) sRed[w]=kcc;
    __syncthreads();
    if(t==0){
        float s=0.f;
        #pragma unroll
        for(int i=0;i<16;i++) s+=sRed[i];
        atomicAdd(&g_kldc,s);
    }
}

__global__ void k_fin(const float* __restrict__ kappa, float* __restrict__ out, int out_size){
    int t=threadIdx.x;
    float a=g_avg[t]*(1.f/(float)NR);
    a=fmaxf(a,1e-10f);
    float term=a*logf(a+1e-10f);
    #pragma unroll
    for(int o=16;o;o>>=1) term+=__shfl_xor_sync(0xffffffffu,term,o);
    __shared__ float ws[16];
    if((t&31)==0) ws[t>>5]=term;
    __syncthreads();
    if(t==0){
        float s=0.f;
        #pragma unroll
        for(int i=0;i<16;i++) s+=ws[i];
        float kq=fminf(fmaxf(kappa[0],1e-5f),1e5f);
        float loss=(g_kldd+g_kldc*kq)*(1.f/32.f);
        if(out_size>=8388609) out[8388608]=loss;
        if(out_size>=8388610) out[8388609]=expf(-s);
    }
}

extern "C" void kernel_launch(void* const* d_in, const int* in_sizes, int n_in,
                              void* d_out, int out_size){
    const float* z=(const float*)d_in[0];
    const float* kappa=(const float*)d_in[1];
    const float* cb=(const float*)d_in[2];
    const float* gu=(const float*)d_in[3];
    float* out=(float*)d_out;
    cudaFuncSetAttribute(k_main, cudaFuncAttributeMaxDynamicSharedMemorySize, SMTOT);
    k_zero<<<1,512>>>();
    k_norm<<<512,256>>>(cb,kappa);
    k_c2<<<256,256>>>();
    k_main<<<512,512,SMTOT>>>(gu,z,out);
    k_fin<<<1,512>>>(kappa,out,out_size);
}

// round 17
// speedup vs baseline: 1.9141x; 1.9141x over previous
#include <cuda_runtime.h>
#include <cuda_bf16.h>
#include <cstdint>
#include <math.h>

#define KD 512
#define DZ 256
#define NR 32768

// smem map (bytes): RA [0,69632)  RB [69632,200704)  MISC [200704,203552)
// GEMM1: RA = A tiles (hi/lo), RB = B1 double buffers
// post:  RA = e bf16 [64][1040B] then sT; RB = B2 fp16 bufs [0,64K) + eg fp16 [64K,128K)
#define RBOFF 69632
#define MISCOFF 200704
#define SMTOT 203552

__device__ __forceinline__ uint32_t s2u(const void* p){
    uint32_t a;
    asm("{ .reg .u64 t; cvta.to.shared.u64 t,%1; cvt.u32.u64 %0,t; }" : "=r"(a) : "l"(p));
    return a;
}
__device__ __forceinline__ void ldsm4(uint32_t r[4], uint32_t a){
    asm volatile("ldmatrix.sync.aligned.m8n8.x4.shared.b16 {%0,%1,%2,%3}, [%4];"
        : "=r"(r[0]),"=r"(r[1]),"=r"(r[2]),"=r"(r[3]) : "r"(a));
}
__device__ __forceinline__ void mma_bf(float d[4], const uint32_t a[4], uint32_t b0, uint32_t b1){
    asm volatile("mma.sync.aligned.m16n8k16.row.col.f32.bf16.bf16.f32 "
        "{%0,%1,%2,%3},{%4,%5,%6,%7},{%8,%9},{%0,%1,%2,%3};"
        : "+f"(d[0]),"+f"(d[1]),"+f"(d[2]),"+f"(d[3])
        : "r"(a[0]),"r"(a[1]),"r"(a[2]),"r"(a[3]),"r"(b0),"r"(b1));
}
__device__ __forceinline__ void mma_f16(float d[4], const uint32_t a[4], uint32_t b0, uint32_t b1){
    asm volatile("mma.sync.aligned.m16n8k16.row.col.f32.f16.f16.f32 "
        "{%0,%1,%2,%3},{%4,%5,%6,%7},{%8,%9},{%0,%1,%2,%3};"
        : "+f"(d[0]),"+f"(d[1]),"+f"(d[2]),"+f"(d[3])
        : "r"(a[0]),"r"(a[1]),"r"(a[2]),"r"(a[3]),"r"(b0),"r"(b1));
}
__device__ __forceinline__ void cpa16(uint32_t dst, const void* src){
    asm volatile("cp.async.cg.shared.global [%0], [%1], 16;" :: "r"(dst), "l"(src));
}
#define CPA_COMMIT() asm volatile("cp.async.commit_group;" ::: "memory")
#define CPA_WAIT0()  asm volatile("cp.async.wait_group 0;" ::: "memory")
#define CPA_WAIT1()  asm volatile("cp.async.wait_group 1;" ::: "memory")
#define PFL2(p)      asm volatile("prefetch.global.L2 [%0];" :: "l"(p))

__device__ __forceinline__ uint32_t packpair(float lo, float hi){
    uint32_t r; asm("cvt.rn.bf16x2.f32 %0, %1, %2;" : "=r"(r) : "f"(hi), "f"(lo)); return r;
}
__device__ __forceinline__ uint32_t packf16(float lo, float hi){
    uint32_t r; asm("cvt.rn.f16x2.f32 %0, %1, %2;" : "=r"(r) : "f"(hi), "f"(lo)); return r;
}
__device__ __forceinline__ float lof(float x){
    return x - __bfloat162float(__float2bfloat16(x));
}
__device__ __forceinline__ void atomicMaxKey(unsigned* a, float f){
    uint32_t b=__float_as_uint(f);
    uint32_t k=(b&0x80000000u)?~b:(b|0x80000000u);
    atomicMax(a,k);
}
__device__ __forceinline__ float decodeKey(unsigned k){
    return __uint_as_float((k&0x80000000u)?(k&0x7fffffffu):~k);
}

__device__ uint32_t g_c1h[KD*128];    // kq*cbn [n=512][kpair=128] bf16 hi
__device__ uint32_t g_c1l[KD*128];    // lo
__device__ uint32_t g_c2f[DZ*256];    // cbn^T  [d=256][jpair=256] fp16
__device__ float    g_cbn[KD*DZ];
__device__ float    g_avg[KD];
__device__ float    g_kldd, g_kldc;

__global__ void k_zero(){
    int t=threadIdx.x;
    if (t<KD) g_avg[t]=0.f;
    if (t==0){ g_kldd=0.f; g_kldc=0.f; }
}

__global__ void k_norm(const float* __restrict__ cb, const float* __restrict__ kappa){
    __shared__ float rowb[256];
    __shared__ float ws[8];
    int j=blockIdx.x, t=threadIdx.x;
    float c=cb[j*DZ+t], s=c*c;
    #pragma unroll
    for(int o=16;o;o>>=1) s += __shfl_xor_sync(0xffffffffu,s,o);
    if((t&31)==0) ws[t>>5]=s;
    __syncthreads();
    float tot=0.f;
    #pragma unroll
    for(int i=0;i<8;i++) tot+=ws[i];
    float cn=c*(1.f/sqrtf(tot));
    g_cbn[j*DZ+t]=cn;
    float kq=fminf(fmaxf(kappa[0],1e-5f),1e5f);
    rowb[t]=cn*kq;
    __syncthreads();
    if(t<128){
        float a=rowb[2*t], b=rowb[2*t+1];
        g_c1h[j*128+t]=packpair(a,b);
        g_c1l[j*128+t]=packpair(lof(a),lof(b));
    }
}

__global__ void k_c2(){
    int d=blockIdx.x, t=threadIdx.x;   // t = jpair
    float a=g_cbn[(2*t)*DZ+d], b=g_cbn[(2*t+1)*DZ+d];
    g_c2f[d*256+t]=packf16(a,b);
}

// ---- GEMM1 staging: k64 chunks, 128B rows, swizzle gr^(n&7) ----
__device__ __forceinline__ void stage_b1(uint32_t smb, int t, int kc, const uint32_t* src, uint32_t dstoff){
    #pragma unroll
    for(int i=0;i<8;i++){
        int q=t+(i<<9); int n=q>>3, gr=q&7;
        cpa16(smb + dstoff + n*128 + ((gr^(n&7))<<4),
              (const char*)src + (size_t)(n*32 + kc*8 + gr)*16);
    }
}
// ---- GEMM2 staging: c2 fp16, k64 chunk = [256 d][128B], swizzle gr^(dd&7) ----
__device__ __forceinline__ void stage_b2f(uint32_t smb, int t, int kc, uint32_t buf){
    #pragma unroll
    for(int i=0;i<4;i++){
        int q=t+(i<<9); int dd=q>>3, gr=q&7;
        cpa16(smb + buf + dd*128 + ((gr^(dd&7))<<4),
              (const char*)g_c2f + (size_t)dd*1024 + kc*128 + gr*16);
    }
}

__global__ __launch_bounds__(512,1)
void k_main(const float* __restrict__ gu, const float* __restrict__ z,
            float* __restrict__ out){
    extern __shared__ char sm[];
    const uint32_t smb=s2u(sm);
    float* MISC=(float*)(sm+MISCOFF);
    float* sZs=MISC; float* sSs=MISC+64; float* sZ2=MISC+128;
    unsigned* sM2=(unsigned*)(MISC+192);
    float* sM2f=(float*)sM2;
    float* sRed=MISC+256;
    const int t=threadIdx.x, lane=t&31, w=t>>5;     // 16 warps
    const int mg=w&1, ns=w>>1;                      // mg 0/1, ns 0..7
    const int g=lane>>2, tq=lane&3;
    const int R0=blockIdx.x<<6;
    if(t<64){ sZs[t]=0.f; sSs[t]=0.f; sZ2[t]=0.f; sM2[t]=0u; }

    const size_t bb=(size_t)(R0>>10);
    const int wh0=R0&1023;
    const float* zb = z + bb*262144 + wh0;

    // ---- prologue: z slab -> RB buf1 (64KB); B1 chunk0 hi -> RB buf0 ----
    #pragma unroll
    for(int i=0;i<8;i++){
        int q=t+(i<<9); int d=q>>4, j4=q&15;
        cpa16(smb + RBOFF + 65536 + (q<<4),
              (const char*)zb + ((size_t)d*4096 + j4*16));
    }
    CPA_COMMIT();
    stage_b1(smb,t,0,g_c1h,RBOFF);       CPA_COMMIT();
    CPA_WAIT1();  __syncthreads();                    // z ready

    // ---- pack A tiles (hi at RA[0,32K), lo at RA[32K,64K)) ----
    {
        const float* sZf=(const float*)(sm + RBOFF + 65536);
        #pragma unroll
        for(int i=0;i<4;i++){
            int m=(t&31)+((i&1)<<5);
            int gr=(t>>5)+((i>>1)<<4);
            float v[8];
            #pragma unroll
            for(int c=0;c<8;c++) v[c]=sZf[(8*gr+c)*64 + m];
            int swz=(gr&24)|((gr^m)&7);
            uint32_t off=(uint32_t)(m*512 + (swz<<4));
            *(uint4*)(sm + off)=make_uint4(packpair(v[0],v[1]),packpair(v[2],v[3]),
                                           packpair(v[4],v[5]),packpair(v[6],v[7]));
            *(uint4*)(sm + 32768 + off)=make_uint4(packpair(lof(v[0]),lof(v[1])),packpair(lof(v[2]),lof(v[3])),
                                                   packpair(lof(v[4]),lof(v[5])),packpair(lof(v[6]),lof(v[7])));
        }
    }
    // gu L2 prefetch (4 rows x 256B per thread)
    {
        const float* p0=gu+(size_t)(R0+mg*32+g)*512+ns*64;
        PFL2(p0); PFL2(p0+32);
        PFL2(p0+8*512); PFL2(p0+8*512+32);
        const float* p2=p0+16*512;
        PFL2(p2); PFL2(p2+32);
        PFL2(p2+8*512); PFL2(p2+8*512+32);
    }
    __syncthreads();                                 // pack done; buf1 free
    stage_b1(smb,t,0,g_c1l,RBOFF+65536); CPA_COMMIT();
    CPA_WAIT1(); __syncthreads();                    // bh(0) ready

    const int sub=lane>>3, rro=(lane&7)+((sub&1)<<3), gpl=sub>>1;

    float a1[2][8][4];
    #pragma unroll
    for(int a=0;a<2;a++)
        #pragma unroll
        for(int b=0;b<8;b++)
            #pragma unroll
            for(int c=0;c<4;c++) a1[a][b][c]=0.f;

    // -------- GEMM1: logits[64][512], k64 chunks, two-phase h/l (R13) --------
    #pragma unroll
    for(int kc=0;kc<4;kc++){
        #pragma unroll
        for(int ks=0;ks<4;ks++){
            int ggA=kc*8+2*ks+gpl, ggB=2*ks+gpl;
            uint32_t ah[2][4], al[2][4];
            #pragma unroll
            for(int mt=0;mt<2;mt++){
                int rr=mg*32+mt*16+rro;
                uint32_t ad=smb + rr*512 + ((((ggA&24)|((ggA^rr)&7)))<<4);
                ldsm4(ah[mt],ad); ldsm4(al[mt],ad+32768);
            }
            #pragma unroll
            for(int nt2=0;nt2<4;nt2++){
                int rrB=ns*64+nt2*16+rro;
                uint32_t bd=smb + RBOFF + rrB*128 + ((ggB^(rrB&7))<<4);
                uint32_t bh[4];
                ldsm4(bh,bd);
                #pragma unroll
                for(int mt=0;mt<2;mt++){
                    mma_bf(a1[mt][2*nt2],   ah[mt], bh[0], bh[2]);
                    mma_bf(a1[mt][2*nt2+1], ah[mt], bh[1], bh[3]);
                    mma_bf(a1[mt][2*nt2],   al[mt], bh[0], bh[2]);
                    mma_bf(a1[mt][2*nt2+1], al[mt], bh[1], bh[3]);
                }
            }
        }
        __syncthreads();
        if(kc<3){ stage_b1(smb,t,kc+1,g_c1h,RBOFF); CPA_COMMIT(); CPA_WAIT1(); }
        else    { CPA_WAIT0(); }
        __syncthreads();                             // bl(kc) ready
        #pragma unroll
        for(int ks=0;ks<4;ks++){
            int ggA=kc*8+2*ks+gpl, ggB=2*ks+gpl;
            uint32_t ah[2][4];
            #pragma unroll
            for(int mt=0;mt<2;mt++){
                int rr=mg*32+mt*16+rro;
                uint32_t ad=smb + rr*512 + ((((ggA&24)|((ggA^rr)&7)))<<4);
                ldsm4(ah[mt],ad);
            }
            #pragma unroll
            for(int nt2=0;nt2<4;nt2++){
                int rrB=ns*64+nt2*16+rro;
                uint32_t bd=smb + RBOFF + 65536 + rrB*128 + ((ggB^(rrB&7))<<4);
                uint32_t bl[4];
                ldsm4(bl,bd);
                #pragma unroll
                for(int mt=0;mt<2;mt++){
                    mma_bf(a1[mt][2*nt2],   ah[mt], bl[0], bl[2]);
                    mma_bf(a1[mt][2*nt2+1], ah[mt], bl[1], bl[3]);
                }
            }
        }
        __syncthreads();
        if(kc<3){ stage_b1(smb,t,kc+1,g_c1l,RBOFF+65536); CPA_COMMIT(); CPA_WAIT1(); __syncthreads(); }
    }

    // ---- B2 fp16 chunk0 staging flows during softmax (RB buf0 free) ----
    stage_b2f(smb,t,0,RBOFF); CPA_COMMIT();

    // -------- softmax pass 1: e (bf16->RA), stats, t2=2(l-lnw) into a1, row max --------
    #pragma unroll
    for(int mt=0;mt<2;mt++){
        int r0=mg*32+mt*16+g, r1=r0+8;
        const float* gur0 = gu + (size_t)(R0+r0)*512 + ns*64 + 2*tq;
        const float* gur1 = gu + (size_t)(R0+r1)*512 + ns*64 + 2*tq;
        float2 nu0=*(const float2*)gur0, nu1=*(const float2*)gur1;
        float Zs0=0,Ss0=0, Zs1=0,Ss1=0;
        float m20=-1e30f, m21=-1e30f;
        #pragma unroll
        for(int nt=0;nt<8;nt++){
            float2 u0=nu0, u1=nu1;
            if(nt<7){ nu0=*(const float2*)(gur0+(nt+1)*8); nu1=*(const float2*)(gur1+(nt+1)*8); }
            int col=ns*64+nt*8+2*tq;
            float* dd=a1[mt][nt];
            float e0=__expf(dd[0]), e1=__expf(dd[1]);
            float e2=__expf(dd[2]), e3=__expf(dd[3]);
            Zs0+=e0+e1; Ss0+=e0*dd[0]+e1*dd[1];
            Zs1+=e2+e3; Ss1+=e2*dd[2]+e3*dd[3];
            *(uint32_t*)(sm + r0*1040 + col*2)=packpair(e0,e1);
            *(uint32_t*)(sm + r1*1040 + col*2)=packpair(e2,e3);
            float w0=-__logf(u0.x+1e-10f), w1=-__logf(u0.y+1e-10f);
            float w2=-__logf(u1.x+1e-10f), w3=-__logf(u1.y+1e-10f);
            dd[0]=2.f*(dd[0]-__logf(w0+1e-10f));
            dd[1]=2.f*(dd[1]-__logf(w1+1e-10f));
            dd[2]=2.f*(dd[2]-__logf(w2+1e-10f));
            dd[3]=2.f*(dd[3]-__logf(w3+1e-10f));
            m20=fmaxf(m20,fmaxf(dd[0],dd[1]));
            m21=fmaxf(m21,fmaxf(dd[2],dd[3]));
        }
        atomicAdd(&sZs[r0],Zs0); atomicAdd(&sSs[r0],Ss0);
        atomicAdd(&sZs[r1],Zs1); atomicAdd(&sSs[r1],Ss1);
        atomicMaxKey(&sM2[r0],m20); atomicMaxKey(&sM2[r1],m21);
    }
    __syncthreads();
    if(t<64){
        float zs=sZs[t], inv=1.f/zs;
        float kd=sSs[t]*inv-__logf(zs);
        sZs[t]=inv;
        sM2f[t]=decodeKey(sM2[t]);
        #pragma unroll
        for(int o=16;o;o>>=1) kd+=__shfl_xor_sync(0xffffffffu,kd,o);
        if(lane==0) atomicAdd(&g_kldd,kd);
    }
    __syncthreads();

    // -------- pass 2: eg' = exp(t2 - m2) -> fp16 smem; Q' row sums --------
    #pragma unroll
    for(int mt=0;mt<2;mt++){
        int r0=mg*32+mt*16+g, r1=r0+8;
        float m20=sM2f[r0], m21=sM2f[r1];
        float Q0=0.f, Q1=0.f;
        #pragma unroll
        for(int nt=0;nt<8;nt++){
            float* dd=a1[mt][nt];
            float g0=__expf(dd[0]-m20), g1=__expf(dd[1]-m20);
            float g2=__expf(dd[2]-m21), g3=__expf(dd[3]-m21);
            Q0+=g0+g1; Q1+=g2+g3;
            int col=ns*64+nt*8+2*tq;
            int gf=col>>3; int swz=(gf&56)|((gf^(r0&7))&7);
            uint32_t off=(uint32_t)(swz<<4)+4*tq;
            *(uint32_t*)(sm + RBOFF + 65536 + r0*1024 + off)=packf16(g0,g1);
            *(uint32_t*)(sm + RBOFF + 65536 + r1*1024 + off)=packf16(g2,g3);
        }
        atomicAdd(&sZ2[r0],Q0); atomicAdd(&sZ2[r1],Q1);
    }
    {   // avg_probs: one column per thread from e bf16 in RA
        float p0=0.f;
        #pragma unroll 8
        for(int r=0;r<64;r++){
            p0=fmaf(__bfloat162float(*(const __nv_bfloat16*)(sm+r*1040+t*2)),sZs[r],p0);
        }
        atomicAdd(&g_avg[t],p0);
    }
    __syncthreads();
    if(t<64) sZ2[t]=1.f/sZ2[t];

    // -------- GEMM2: zq[64][256] = eg' @ cbn, fp16 single-pass, k64 chunks --------
    float a2[2][4][4];
    #pragma unroll
    for(int a=0;a<2;a++)
        #pragma unroll
        for(int b=0;b<4;b++)
            #pragma unroll
            for(int c=0;c<4;c++) a2[a][b][c]=0.f;

    #pragma unroll
    for(int kc=0;kc<8;kc++){
        const uint32_t buf = RBOFF + (uint32_t)(kc&1)*32768;
        CPA_WAIT0(); __syncthreads();
        if(kc<7){ stage_b2f(smb,t,kc+1,RBOFF + (uint32_t)((kc&1)^1)*32768); CPA_COMMIT(); }
        #pragma unroll
        for(int ks=0;ks<4;ks++){
            int ggE=kc*8+2*ks+gpl, ggB=2*ks+gpl;
            uint32_t eh[2][4];
            #pragma unroll
            for(int mt=0;mt<2;mt++){
                int rr=mg*32+mt*16+rro;
                uint32_t ad=smb + RBOFF + 65536 + rr*1024 + ((((ggE&56)|((ggE^rr)&7)))<<4);
                ldsm4(eh[mt],ad);
            }
            #pragma unroll
            for(int nt2=0;nt2<2;nt2++){
                int rrB=ns*32+nt2*16+rro;
                uint32_t bd=smb + buf + rrB*128 + ((ggB^(rrB&7))<<4);
                uint32_t bh[4];
                ldsm4(bh,bd);
                #pragma unroll
                for(int mt=0;mt<2;mt++){
                    mma_f16(a2[mt][2*nt2],   eh[mt], bh[0], bh[2]);
                    mma_f16(a2[mt][2*nt2+1], eh[mt], bh[1], bh[3]);
                }
            }
        }
    }
    __syncthreads();

    // -------- epilogue: scale by 1/Q', transpose, coalesced store + kldc --------
    float* sT=(float*)sm;   // [256 d][66]
    #pragma unroll
    for(int mt=0;mt<2;mt++){
        int r0=mg*32+mt*16+g, r1=r0+8;
        float zi0=sZ2[r0], zi1=sZ2[r1];
        #pragma unroll
        for(int nt=0;nt<4;nt++){
            int d0=ns*32+nt*8+2*tq;
            float* dd=a2[mt][nt];
            sT[d0*66+r0]=dd[0]*zi0; sT[(d0+1)*66+r0]=dd[1]*zi0;
            sT[d0*66+r1]=dd[2]*zi1; sT[(d0+1)*66+r1]=dd[3]*zi1;
        }
    }
    __syncthreads();
    size_t base=bb*262144 + (size_t)wh0;
    float kcc=0.f;
    #pragma unroll
    for(int i=0;i<32;i++){
        int q=t+(i<<9); int d=q>>6, r=q&63;
        float v=sT[d*66+r];
        size_t gi=base+(size_t)d*1024+r;
        float zv=z[gi];
        out[gi]=v;
        kcc=fmaf(zv,zv-v,kcc);
    }
    #pragma unroll
    for(int o=16;o;o>>=1) kcc+=__shfl_xor_sync(0xffffffffu,kcc,o);
    if(lane==0) sRed[w]=kcc;
    __syncthreads();
    if(t==0){
        float s=0.f;
        #pragma unroll
        for(int i=0;i<16;i++) s+=sRed[i];
        atomicAdd(&g_kldc,s);
    }
}

__global__ void k_fin(const float* __restrict__ kappa, float* __restrict__ out, int out_size){
    int t=threadIdx.x;
    float a=g_avg[t]*(1.f/(float)NR);
    a=fmaxf(a,1e-10f);
    float term=a*logf(a+1e-10f);
    #pragma unroll
    for(int o=16;o;o>>=1) term+=__shfl_xor_sync(0xffffffffu,term,o);
    __shared__ float ws[16];
    if((t&31)==0) ws[t>>5]=term;
    __syncthreads();
    if(t==0){
        float s=0.f;
        #pragma unroll
        for(int i=0;i<16;i++) s+=ws[i];
        float kq=fminf(fmaxf(kappa[0],1e-5f),1e5f);
        float loss=(g_kldd+g_kldc*kq)*(1.f/32.f);
        if(out_size>=8388609) out[8388608]=loss;
        if(out_size>=8388610) out[8388609]=expf(-s);
    }
}

extern "C" void kernel_launch(void* const* d_in, const int* in_sizes, int n_in,
                              void* d_out, int out_size){
    const float* z=(const float*)d_in[0];
    const float* kappa=(const float*)d_in[1];
    const float* cb=(const float*)d_in[2];
    const float* gu=(const float*)d_in[3];
    float* out=(float*)d_out;
    cudaFuncSetAttribute(k_main, cudaFuncAttributeMaxDynamicSharedMemorySize, SMTOT);
    k_zero<<<1,512>>>();
    k_norm<<<512,256>>>(cb,kappa);
    k_c2<<<256,256>>>();
    k_main<<<512,512,SMTOT>>>(gu,z,out);
    k_fin<<<1,512>>>(kappa,out,out_size);
}